// round 1
// baseline (speedup 1.0000x reference)
#include <cuda_runtime.h>
#include <cuda_bf16.h>

#define HID 64
#define NB  32
#define TPB 128

typedef unsigned long long ull;

// ---- packed fp32x2 helpers (Blackwell dual-issue fp32 pipe) ----
__device__ __forceinline__ ull dup2(float a) {
    ull r; asm("mov.b64 %0,{%1,%1};" : "=l"(r) : "f"(a)); return r;
}
__device__ __forceinline__ void up2(ull v, float& a, float& b) {
    asm("mov.b64 {%0,%1},%2;" : "=f"(a), "=f"(b) : "l"(v));
}
__device__ __forceinline__ void fma2(ull& d, ull a, ull b) {
    asm("fma.rn.f32x2 %0,%1,%2,%0;" : "+l"(d) : "l"(a), "l"(b));
}
// vectorized no-return global atomic add (sm_90+)
__device__ __forceinline__ void red4(float* p, float a, float b, float c, float d) {
    asm volatile("red.global.add.v4.f32 [%0],{%1,%2,%3,%4};"
                 :: "l"(p), "f"(a), "f"(b), "f"(c), "f"(d) : "memory");
}
__device__ __forceinline__ float silu_f(float y) {
    return __fdividef(y, 1.f + __expf(-y));
}

// shared layout (floats)
#define OFF_W1 0                      // 2 * 32*64
#define OFF_W2 4096                   // 2 * 64*64
#define OFF_B1 12288                  // 2 * 64
#define OFF_B2 12416                  // 2 * 64
#define OFF_XS 12544                  // 32 * TPB  (per-thread x scratch, [k][tid])
#define OFF_HS (12544 + NB * TPB)     // 64 * TPB  (per-thread h scratch, [k][tid])
#define SMEM_FLOATS (OFF_HS + HID * TPB)
#define SMEM_BYTES  (SMEM_FLOATS * 4)

__global__ void __launch_bounds__(TPB) tpc_edge_kernel(
    const float* __restrict__ scalar, const float* __restrict__ vec,
    const float* __restrict__ elen,   const int* __restrict__ eidx,
    const float* __restrict__ sw1, const float* __restrict__ sb1,
    const float* __restrict__ sw2, const float* __restrict__ sb2,
    const float* __restrict__ vw1, const float* __restrict__ vb1,
    const float* __restrict__ vw2, const float* __restrict__ vb2,
    float* __restrict__ out, int E, long long nscal)
{
    extern __shared__ float smf[];
    int tid = threadIdx.x;

    // ---- stage weights into SMEM (float4 copies) ----
    {
        const float4* s1 = (const float4*)sw1;
        const float4* v1 = (const float4*)vw1;
        float4* d1 = (float4*)(smf + OFF_W1);
        for (int i = tid; i < NB * HID / 4; i += TPB) {
            d1[i] = s1[i];
            d1[i + NB * HID / 4] = v1[i];
        }
        const float4* s2 = (const float4*)sw2;
        const float4* v2 = (const float4*)vw2;
        float4* d2 = (float4*)(smf + OFF_W2);
        for (int i = tid; i < HID * HID / 4; i += TPB) {
            d2[i] = s2[i];
            d2[i + HID * HID / 4] = v2[i];
        }
        if (tid < HID) {
            smf[OFF_B1 + tid]       = sb1[tid];
            smf[OFF_B1 + HID + tid] = vb1[tid];
            smf[OFF_B2 + tid]       = sb2[tid];
            smf[OFF_B2 + HID + tid] = vb2[tid];
        }
    }
    __syncthreads();

    int e = blockIdx.x * TPB + tid;
    if (e >= E) return;

    int row = eidx[e];       // destination (segment id)
    int col = eidx[E + e];   // source (gather id)

    // ---- stage x (radial basis) to per-thread SMEM columns ----
    {
        const float4* xp = (const float4*)(elen + (size_t)e * NB);
        #pragma unroll
        for (int i = 0; i < NB / 4; i++) {
            float4 v = xp[i];
            smf[OFF_XS + (4 * i + 0) * TPB + tid] = v.x;
            smf[OFF_XS + (4 * i + 1) * TPB + tid] = v.y;
            smf[OFF_XS + (4 * i + 2) * TPB + tid] = v.z;
            smf[OFF_XS + (4 * i + 3) * TPB + tid] = v.w;
        }
    }

    const float* srcS = scalar + (size_t)col * HID;
    const float* srcV = vec + (size_t)col * 3 * HID;
    float* dstS = out + (size_t)row * HID;
    float* dstV = out + nscal + (size_t)row * 3 * HID;

    #pragma unroll 1
    for (int m = 0; m < 2; m++) {
        const float* w1m = smf + OFF_W1 + m * (NB * HID);
        const float* w2m = smf + OFF_W2 + m * (HID * HID);
        const ull* b1m = (const ull*)(smf + OFF_B1 + m * HID);
        const ull* b2m = (const ull*)(smf + OFF_B2 + m * HID);

        // ---- layer 1: h = silu(x @ w1 + b1), 32 paired accumulators ----
        ull acc[HID / 2];
        #pragma unroll
        for (int j = 0; j < HID / 2; j++) acc[j] = b1m[j];

        #pragma unroll 4
        for (int k = 0; k < NB; k++) {
            ull xd = dup2(smf[OFF_XS + k * TPB + tid]);
            const ulonglong2* pw = (const ulonglong2*)(w1m + k * HID);
            #pragma unroll
            for (int q = 0; q < HID / 4; q++) {
                ulonglong2 wv = pw[q];
                fma2(acc[2 * q], xd, wv.x);
                fma2(acc[2 * q + 1], xd, wv.y);
            }
        }
        #pragma unroll
        for (int j = 0; j < HID / 2; j++) {
            float a, b; up2(acc[j], a, b);
            smf[OFF_HS + (2 * j) * TPB + tid]     = silu_f(a);
            smf[OFF_HS + (2 * j + 1) * TPB + tid] = silu_f(b);
        }

        // ---- layer 2 in 4 output tiles of 16, fused gather+weight+scatter ----
        #pragma unroll 1
        for (int jt = 0; jt < 4; jt++) {
            int j0 = jt * 16;

            // issue gathers early; the 64-step k-loop hides their latency
            float4 gs[4]; float4 gv[12];
            if (m == 0) {
                const float4* p = (const float4*)(srcS + j0);
                #pragma unroll
                for (int q = 0; q < 4; q++) gs[q] = p[q];
            } else {
                #pragma unroll
                for (int d = 0; d < 3; d++) {
                    const float4* p = (const float4*)(srcV + d * HID + j0);
                    #pragma unroll
                    for (int q = 0; q < 4; q++) gv[d * 4 + q] = p[q];
                }
            }

            ull a2[8];
            #pragma unroll
            for (int q = 0; q < 8; q++) a2[q] = b2m[j0 / 2 + q];

            #pragma unroll 8
            for (int k = 0; k < HID; k++) {
                ull hd = dup2(smf[OFF_HS + k * TPB + tid]);
                const ulonglong2* pw = (const ulonglong2*)(w2m + k * HID + j0);
                #pragma unroll
                for (int q = 0; q < 4; q++) {
                    ulonglong2 wv = pw[q];
                    fma2(a2[2 * q], hd, wv.x);
                    fma2(a2[2 * q + 1], hd, wv.y);
                }
            }

            float w[16];
            #pragma unroll
            for (int q = 0; q < 8; q++) up2(a2[q], w[2 * q], w[2 * q + 1]);

            if (m == 0) {
                #pragma unroll
                for (int q = 0; q < 4; q++) {
                    float4 s = gs[q];
                    red4(dstS + j0 + 4 * q,
                         s.x * w[4 * q], s.y * w[4 * q + 1],
                         s.z * w[4 * q + 2], s.w * w[4 * q + 3]);
                }
            } else {
                #pragma unroll
                for (int d = 0; d < 3; d++) {
                    #pragma unroll
                    for (int q = 0; q < 4; q++) {
                        float4 v = gv[d * 4 + q];
                        red4(dstV + d * HID + j0 + 4 * q,
                             v.x * w[4 * q], v.y * w[4 * q + 1],
                             v.z * w[4 * q + 2], v.w * w[4 * q + 3]);
                    }
                }
            }
        }
    }
}

extern "C" void kernel_launch(void* const* d_in, const int* in_sizes, int n_in,
                              void* d_out, int out_size)
{
    const float* scalar = (const float*)d_in[0];
    const float* vec    = (const float*)d_in[1];
    // d_in[2] = edge_sh (unused by the reference)
    const float* elen   = (const float*)d_in[3];
    const int*   eidx   = (const int*)d_in[4];
    const float* sw1 = (const float*)d_in[5];
    const float* sb1 = (const float*)d_in[6];
    const float* sw2 = (const float*)d_in[7];
    const float* sb2 = (const float*)d_in[8];
    const float* vw1 = (const float*)d_in[9];
    const float* vb1 = (const float*)d_in[10];
    const float* vw2 = (const float*)d_in[11];
    const float* vb2 = (const float*)d_in[12];

    int E  = in_sizes[3] / NB;              // 500000
    int Nn = in_sizes[0] / HID;             // 50000
    long long nscal = (long long)Nn * HID;  // offset of out_vector in d_out

    // zero accumulation buffer (d_out is poisoned before timing)
    cudaMemsetAsync(d_out, 0, (size_t)out_size * sizeof(float));

    cudaFuncSetAttribute(tpc_edge_kernel,
                         cudaFuncAttributeMaxDynamicSharedMemorySize, SMEM_BYTES);

    int blocks = (E + TPB - 1) / TPB;
    tpc_edge_kernel<<<blocks, TPB, SMEM_BYTES>>>(
        scalar, vec, elen, eidx,
        sw1, sb1, sw2, sb2, vw1, vb1, vw2, vb2,
        (float*)d_out, E, nscal);
}